// round 13
// baseline (speedup 1.0000x reference)
#include <cuda_runtime.h>
#include <cuda_bf16.h>
#include <mma.h>
#include <cstdint>

using namespace nvcuda;

#define N_NODES 10000
#define N_EDGES 163840
#define IN_SIZE 512
#define H_SIZE 512
#define OUT_SIZE 64
#define M_PAD 10112   // padded row count (>= ceil(10000/128)*128)

// ---------------- scratch (device globals; no allocation allowed) ----------
// g_cnt starts zero (static zero-init); k_scan re-zeros it after consuming,
// so it is zero before k_hist on every graph replay.
__device__ float g_dinv[N_NODES];
__device__ int   g_cnt[N_NODES];
__device__ int   g_rowptr[N_NODES + 1];
__device__ int   g_cursor[N_NODES];
__device__ int   g_csrc[N_EDGES];
__device__ float g_h1[(size_t)M_PAD * H_SIZE];   // x@W1 (raw)
__device__ float g_y[(size_t)M_PAD * H_SIZE];    // relu(Â h1 + b1)
__device__ float g_h2[(size_t)M_PAD * OUT_SIZE]; // y@W2 (raw)

// ---------------- CSR build -------------------------------------------------
__global__ void k_hist(const int* __restrict__ dst, int* cnt) {
    int e = blockIdx.x * blockDim.x + threadIdx.x;
    if (e < N_EDGES) atomicAdd(&cnt[dst[e]], 1);
}

// single-block scan (warp-shuffle, 2 barriers) over 10000 counts.
#define SCAN_T 1024
#define SCAN_E 10
__global__ __launch_bounds__(SCAN_T)
void k_scan(int* cnt, int* rowptr, int* cursor, float* dinv) {
    __shared__ int wsum[32];
    const int t = threadIdx.x;
    const int lane = t & 31;
    const int wid = t >> 5;
    const int base = t * SCAN_E;

    int c[SCAN_E];
    int s = 0;
#pragma unroll
    for (int i = 0; i < SCAN_E; i++) {
        int idx = base + i;
        c[i] = (idx < N_NODES) ? cnt[idx] : 0;
        s += c[i];
    }
    int ws = s;
#pragma unroll
    for (int o = 1; o < 32; o <<= 1) {
        int v = __shfl_up_sync(0xffffffffu, ws, o);
        if (lane >= o) ws += v;
    }
    if (lane == 31) wsum[wid] = ws;
    __syncthreads();
    if (wid == 0) {
        int v = wsum[lane];
#pragma unroll
        for (int o = 1; o < 32; o <<= 1) {
            int u = __shfl_up_sync(0xffffffffu, v, o);
            if (lane >= o) v += u;
        }
        wsum[lane] = v;
    }
    __syncthreads();

    int warp_excl = (wid == 0) ? 0 : wsum[wid - 1];
    int run = warp_excl + ws - s;
#pragma unroll
    for (int i = 0; i < SCAN_E; i++) {
        int idx = base + i;
        if (idx < N_NODES) {
            rowptr[idx] = run;
            cursor[idx] = run;
            dinv[idx] = rsqrtf((float)(c[i] + 1));  // +1 self loop
            cnt[idx] = 0;                            // re-zero for next replay
            run += c[i];
        }
    }
    if (t == SCAN_T - 1) rowptr[N_NODES] = wsum[31];
}

__global__ void k_fill(const int* __restrict__ src, const int* __restrict__ dst,
                       int* cursor, int* csrc) {
    int e = blockIdx.x * blockDim.x + threadIdx.x;
    if (e >= N_EDGES) return;
    int d = dst[e];
    int pos = atomicAdd(&cursor[d], 1);
    csrc[pos] = src[e];
}

// ---------------- TF32 WMMA GEMM (sync loads, single buffer) ----------------
// fp32->tf32 RN conversion happens in the smem fill path (R9-measured best).
// C rows are padded (stores unguarded); A rows >= M read as zero.
template <int BM, int BN, int BK, int WM, int WN>
__global__ __launch_bounds__(256)
void k_wmma(const float* __restrict__ A, const float* __restrict__ B,
            float* __restrict__ C, int M, int N, int K) {
    constexpr int LDA = BK + 4;
    constexpr int LDB = BN + 4;
    constexpr int WTM = BM / WM;
    constexpr int WTN = BN / WN;
    constexpr int FM = WTM / 16;
    constexpr int FN = WTN / 16;
    __shared__ float As[BM * LDA];
    __shared__ float Bs[BK * LDB];

    const int tid = threadIdx.x;
    const int wid = tid >> 5;
    const int wm = wid % WM;
    const int wn = wid / WM;
    const int bm = blockIdx.x * BM;
    const int bn = blockIdx.y * BN;

    wmma::fragment<wmma::accumulator, 16, 16, 8, float> acc[FM][FN];
#pragma unroll
    for (int fm = 0; fm < FM; fm++)
#pragma unroll
        for (int fn = 0; fn < FN; fn++) wmma::fill_fragment(acc[fm][fn], 0.0f);

    constexpr int LA = (BM * BK) / (4 * 256);
    constexpr int LB = (BK * BN) / (4 * 256);

    for (int k0 = 0; k0 < K; k0 += BK) {
#pragma unroll
        for (int i = 0; i < LA; i++) {
            int idx = tid + i * 256;
            int row = idx / (BK / 4);
            int c4 = (idx % (BK / 4)) * 4;
            float4 v = make_float4(0.f, 0.f, 0.f, 0.f);
            if (bm + row < M)
                v = *reinterpret_cast<const float4*>(&A[(size_t)(bm + row) * K + k0 + c4]);
            As[row * LDA + c4 + 0] = wmma::__float_to_tf32(v.x);
            As[row * LDA + c4 + 1] = wmma::__float_to_tf32(v.y);
            As[row * LDA + c4 + 2] = wmma::__float_to_tf32(v.z);
            As[row * LDA + c4 + 3] = wmma::__float_to_tf32(v.w);
        }
#pragma unroll
        for (int i = 0; i < LB; i++) {
            int idx = tid + i * 256;
            int kr = idx / (BN / 4);
            int c4 = (idx % (BN / 4)) * 4;
            float4 v = *reinterpret_cast<const float4*>(&B[(size_t)(k0 + kr) * N + bn + c4]);
            Bs[kr * LDB + c4 + 0] = wmma::__float_to_tf32(v.x);
            Bs[kr * LDB + c4 + 1] = wmma::__float_to_tf32(v.y);
            Bs[kr * LDB + c4 + 2] = wmma::__float_to_tf32(v.z);
            Bs[kr * LDB + c4 + 3] = wmma::__float_to_tf32(v.w);
        }
        __syncthreads();

#pragma unroll
        for (int kk = 0; kk < BK; kk += 8) {
            wmma::fragment<wmma::matrix_a, 16, 16, 8, wmma::precision::tf32, wmma::row_major> af[FM];
            wmma::fragment<wmma::matrix_b, 16, 16, 8, wmma::precision::tf32, wmma::row_major> bf[FN];
#pragma unroll
            for (int fm = 0; fm < FM; fm++)
                wmma::load_matrix_sync(af[fm], &As[(wm * WTM + fm * 16) * LDA + kk], LDA);
#pragma unroll
            for (int fn = 0; fn < FN; fn++)
                wmma::load_matrix_sync(bf[fn], &Bs[kk * LDB + wn * WTN + fn * 16], LDB);
#pragma unroll
            for (int fm = 0; fm < FM; fm++)
#pragma unroll
                for (int fn = 0; fn < FN; fn++)
                    wmma::mma_sync(acc[fm][fn], af[fm], bf[fn], acc[fm][fn]);
        }
        __syncthreads();
    }

#pragma unroll
    for (int fm = 0; fm < FM; fm++)
#pragma unroll
        for (int fn = 0; fn < FN; fn++)
            wmma::store_matrix_sync(
                &C[(size_t)(bm + wm * WTM + fm * 16) * N + bn + wn * WTN + fn * 16],
                acc[fm][fn], N, wmma::mem_row_major);
}

// ---------------- layer-1 aggregate (CSR gather) + self + bias + relu -------
__global__ __launch_bounds__(256)
void k_agg1(const int* __restrict__ rowptr, const int* __restrict__ csrc,
            const float* __restrict__ dinv, const float* __restrict__ h1,
            const float* __restrict__ b1, float* __restrict__ y) {
    int node = (blockIdx.x * blockDim.x + threadIdx.x) >> 5;
    if (node >= N_NODES) return;
    int lane = threadIdx.x & 31;
    int beg = __ldg(&rowptr[node]);
    int end = __ldg(&rowptr[node + 1]);
    float dd = __ldg(&dinv[node]);

    float4 a0 = {0, 0, 0, 0}, a1 = {0, 0, 0, 0}, a2 = {0, 0, 0, 0}, a3 = {0, 0, 0, 0};
    const float4* H = reinterpret_cast<const float4*>(h1);
    for (int j = beg; j < end; j++) {
        int s = __ldg(&csrc[j]);
        float nrm = dd * __ldg(&dinv[s]);
        const float4* hp = H + (size_t)s * 128;
        float4 v0 = __ldg(hp + lane);
        float4 v1 = __ldg(hp + lane + 32);
        float4 v2 = __ldg(hp + lane + 64);
        float4 v3 = __ldg(hp + lane + 96);
        a0.x += v0.x * nrm; a0.y += v0.y * nrm; a0.z += v0.z * nrm; a0.w += v0.w * nrm;
        a1.x += v1.x * nrm; a1.y += v1.y * nrm; a1.z += v1.z * nrm; a1.w += v1.w * nrm;
        a2.x += v2.x * nrm; a2.y += v2.y * nrm; a2.z += v2.z * nrm; a2.w += v2.w * nrm;
        a3.x += v3.x * nrm; a3.y += v3.y * nrm; a3.z += v3.z * nrm; a3.w += v3.w * nrm;
    }
    float w = dd * dd;
    const float4* hs = H + (size_t)node * 128;
    const float4* B4 = reinterpret_cast<const float4*>(b1);
    float4* Y = reinterpret_cast<float4*>(y) + (size_t)node * 128;
    float4 accs[4] = {a0, a1, a2, a3};
#pragma unroll
    for (int kchunk = 0; kchunk < 4; kchunk++) {
        int off = lane + kchunk * 32;
        float4 h = __ldg(hs + off);
        float4 b = __ldg(B4 + off);
        float4 r;
        r.x = fmaxf(accs[kchunk].x + h.x * w + b.x, 0.f);
        r.y = fmaxf(accs[kchunk].y + h.y * w + b.y, 0.f);
        r.z = fmaxf(accs[kchunk].z + h.z * w + b.z, 0.f);
        r.w = fmaxf(accs[kchunk].w + h.w * w + b.w, 0.f);
        Y[off] = r;
    }
}

// ---------------- layer-2 aggregate + self + bias + log_softmax -> out ------
__global__ __launch_bounds__(256)
void k_agg2(const int* __restrict__ rowptr, const int* __restrict__ csrc,
            const float* __restrict__ dinv, const float* __restrict__ h2,
            const float* __restrict__ b2, float* __restrict__ out) {
    int node = (blockIdx.x * blockDim.x + threadIdx.x) >> 5;
    if (node >= N_NODES) return;
    int lane = threadIdx.x & 31;
    int beg = __ldg(&rowptr[node]);
    int end = __ldg(&rowptr[node + 1]);
    float dd = __ldg(&dinv[node]);

    float2 acc = {0, 0};
    const float2* H2 = reinterpret_cast<const float2*>(h2);
    for (int j = beg; j < end; j++) {
        int s = __ldg(&csrc[j]);
        float nrm = dd * __ldg(&dinv[s]);
        float2 v = __ldg(H2 + (size_t)s * 32 + lane);
        acc.x += v.x * nrm;
        acc.y += v.y * nrm;
    }
    float w = dd * dd;
    float2 hv = __ldg(H2 + (size_t)node * 32 + lane);
    float2 bv = reinterpret_cast<const float2*>(b2)[lane];
    float v0 = acc.x + hv.x * w + bv.x;
    float v1 = acc.y + hv.y * w + bv.y;

    size_t base = (size_t)node * OUT_SIZE;
    out[base + 2 * lane] = v0;
    out[base + 2 * lane + 1] = v1;

    float m = fmaxf(v0, v1);
#pragma unroll
    for (int o = 16; o > 0; o >>= 1) m = fmaxf(m, __shfl_xor_sync(0xffffffffu, m, o));
    float s = expf(v0 - m) + expf(v1 - m);
#pragma unroll
    for (int o = 16; o > 0; o >>= 1) s += __shfl_xor_sync(0xffffffffu, s, o);
    float lse = m + logf(s);
    const size_t half = (size_t)N_NODES * OUT_SIZE;
    out[half + base + 2 * lane] = v0 - lse;
    out[half + base + 2 * lane + 1] = v1 - lse;
}

// ---------------- launch ----------------------------------------------------
extern "C" void kernel_launch(void* const* d_in, const int* in_sizes, int n_in,
                              void* d_out, int out_size) {
    const float* x  = (const float*)d_in[0];
    const int*   ei = (const int*)d_in[1];   // [2, E]: src row then dst row
    const float* W1 = (const float*)d_in[2];
    const float* b1 = (const float*)d_in[3];
    const float* W2 = (const float*)d_in[4];
    const float* b2 = (const float*)d_in[5];
    float* out = (float*)d_out;

    const int* src = ei;
    const int* dst = ei + N_EDGES;

    float *dinv, *h1, *y, *h2;
    int *cnt, *rowptr, *cursor, *csrc;
    cudaGetSymbolAddress((void**)&dinv,   g_dinv);
    cudaGetSymbolAddress((void**)&cnt,    g_cnt);
    cudaGetSymbolAddress((void**)&rowptr, g_rowptr);
    cudaGetSymbolAddress((void**)&cursor, g_cursor);
    cudaGetSymbolAddress((void**)&csrc,   g_csrc);
    cudaGetSymbolAddress((void**)&h1,     g_h1);
    cudaGetSymbolAddress((void**)&y,      g_y);
    cudaGetSymbolAddress((void**)&h2,     g_h2);

    // Side stream + fork/join events (created per call, never destroyed:
    // destroying a capture-participating stream would invalidate the capture;
    // ~3 calls total -> negligible host-handle leak, zero device memory).
    cudaStream_t s2;
    cudaStreamCreateWithFlags(&s2, cudaStreamNonBlocking);
    cudaEvent_t evFork, evJoin;
    cudaEventCreateWithFlags(&evFork, cudaEventDisableTiming);
    cudaEventCreateWithFlags(&evJoin, cudaEventDisableTiming);

    // fork: CSR chain on s2, concurrent with GEMM1 on the main stream
    cudaEventRecord(evFork, 0);
    cudaStreamWaitEvent(s2, evFork, 0);

    k_hist<<<(N_EDGES + 255) / 256, 256, 0, s2>>>(dst, cnt);
    k_scan<<<1, SCAN_T, 0, s2>>>(cnt, rowptr, cursor, dinv);
    k_fill<<<(N_EDGES + 255) / 256, 256, 0, s2>>>(src, dst, cursor, csrc);
    cudaEventRecord(evJoin, s2);

    // GEMM1 on main stream: h1 = x @ W1  — 128x128 tile, 316 CTAs ≈ 1 wave
    {
        dim3 grid((N_NODES + 127) / 128, H_SIZE / 128);
        k_wmma<128, 128, 32, 4, 2><<<grid, 256>>>(x, W1, h1, N_NODES, H_SIZE, IN_SIZE);
    }

    // join: aggregation needs both GEMM1 (main) and CSR (s2)
    cudaStreamWaitEvent(0, evJoin, 0);

    // layer-1 aggregation + relu
    k_agg1<<<(N_NODES * 32 + 255) / 256, 256>>>(rowptr, csrc, dinv, h1, b1, y);

    // GEMM2: h2 = y @ W2   [10000,512]x[512,64]
    {
        dim3 grid((N_NODES + 63) / 64, OUT_SIZE / 64);
        k_wmma<64, 64, 32, 2, 4><<<grid, 256>>>(y, W2, h2, N_NODES, OUT_SIZE, H_SIZE);
    }

    // layer-2 aggregation + bias + log_softmax -> out
    k_agg2<<<(N_NODES * 32 + 255) / 256, 256>>>(rowptr, csrc, dinv, h2, b2, out);
}

// round 14
// speedup vs baseline: 1.7116x; 1.7116x over previous
#include <cuda_runtime.h>
#include <cuda_fp16.h>
#include <mma.h>
#include <cstdint>

using namespace nvcuda;

#define N_NODES 10000
#define N_EDGES 163840
#define IN_SIZE 512
#define H_SIZE 512
#define OUT_SIZE 64
#define M_PAD 10112   // padded row count (>= ceil(10000/128)*128)

// ---------------- scratch (device globals; no allocation allowed) ----------
// g_cnt starts zero (static zero-init); k_scan re-zeros it after consuming,
// so it is zero before k_hist on every graph replay.
__device__ float g_dinv[N_NODES];
__device__ int   g_cnt[N_NODES];
__device__ int   g_rowptr[N_NODES + 1];
__device__ int   g_cursor[N_NODES];
__device__ int   g_csrc[N_EDGES];
__device__ float g_h1[(size_t)M_PAD * H_SIZE];   // x@W1 (raw fp32 accum)
__device__ float g_y[(size_t)M_PAD * H_SIZE];    // relu(Â h1 + b1)
__device__ float g_h2[(size_t)M_PAD * OUT_SIZE]; // y@W2 (raw fp32 accum)

// ---------------- CSR build -------------------------------------------------
__global__ void k_hist(const int* __restrict__ dst, int* cnt) {
    int e = blockIdx.x * blockDim.x + threadIdx.x;
    if (e < N_EDGES) atomicAdd(&cnt[dst[e]], 1);
}

// single-block scan (warp-shuffle, 2 barriers) over 10000 counts.
#define SCAN_T 1024
#define SCAN_E 10
__global__ __launch_bounds__(SCAN_T)
void k_scan(int* cnt, int* rowptr, int* cursor, float* dinv) {
    __shared__ int wsum[32];
    const int t = threadIdx.x;
    const int lane = t & 31;
    const int wid = t >> 5;
    const int base = t * SCAN_E;

    int c[SCAN_E];
    int s = 0;
#pragma unroll
    for (int i = 0; i < SCAN_E; i++) {
        int idx = base + i;
        c[i] = (idx < N_NODES) ? cnt[idx] : 0;
        s += c[i];
    }
    int ws = s;
#pragma unroll
    for (int o = 1; o < 32; o <<= 1) {
        int v = __shfl_up_sync(0xffffffffu, ws, o);
        if (lane >= o) ws += v;
    }
    if (lane == 31) wsum[wid] = ws;
    __syncthreads();
    if (wid == 0) {
        int v = wsum[lane];
#pragma unroll
        for (int o = 1; o < 32; o <<= 1) {
            int u = __shfl_up_sync(0xffffffffu, v, o);
            if (lane >= o) v += u;
        }
        wsum[lane] = v;
    }
    __syncthreads();

    int warp_excl = (wid == 0) ? 0 : wsum[wid - 1];
    int run = warp_excl + ws - s;
#pragma unroll
    for (int i = 0; i < SCAN_E; i++) {
        int idx = base + i;
        if (idx < N_NODES) {
            rowptr[idx] = run;
            cursor[idx] = run;
            dinv[idx] = rsqrtf((float)(c[i] + 1));  // +1 self loop
            cnt[idx] = 0;                            // re-zero for next replay
            run += c[i];
        }
    }
    if (t == SCAN_T - 1) rowptr[N_NODES] = wsum[31];
}

__global__ void k_fill(const int* __restrict__ src, const int* __restrict__ dst,
                       int* cursor, int* csrc) {
    int e = blockIdx.x * blockDim.x + threadIdx.x;
    if (e >= N_EDGES) return;
    int d = dst[e];
    int pos = atomicAdd(&cursor[d], 1);
    csrc[pos] = src[e];
}

// ---------------- FP16 WMMA GEMM (sync loads, single buffer) ----------------
// fp32 inputs are RN-rounded to fp16 in the smem fill path; fp32 accumulate.
// fp16 mantissa (10 bits + RN) == tf32 mantissa -> same quantization error as
// the measured tf32 pipeline; range is fine for this workload (values O(1)).
// m16n16k16: half the MMA instrs + half the smem bytes vs tf32 m16n16k8.
// C rows are padded (stores unguarded); A rows >= M read as zero.
template <int BM, int BN, int BK, int WM, int WN>
__global__ __launch_bounds__(256)
void k_hgemm(const float* __restrict__ A, const float* __restrict__ B,
             float* __restrict__ C, int M, int N, int K) {
    constexpr int LDA = BK + 8;   // halves; multiple of 8 for wmma ldm
    constexpr int LDB = BN + 8;
    constexpr int WTM = BM / WM;
    constexpr int WTN = BN / WN;
    constexpr int FM = WTM / 16;
    constexpr int FN = WTN / 16;
    __shared__ __half As[BM * LDA];
    __shared__ __half Bs[BK * LDB];

    const int tid = threadIdx.x;
    const int wid = tid >> 5;
    const int wm = wid % WM;
    const int wn = wid / WM;
    const int bm = blockIdx.x * BM;
    const int bn = blockIdx.y * BN;

    wmma::fragment<wmma::accumulator, 16, 16, 16, float> acc[FM][FN];
#pragma unroll
    for (int fm = 0; fm < FM; fm++)
#pragma unroll
        for (int fn = 0; fn < FN; fn++) wmma::fill_fragment(acc[fm][fn], 0.0f);

    constexpr int LA = (BM * BK) / (4 * 256);   // float4 (4 elem) chunks of A
    constexpr int LB = (BK * BN) / (4 * 256);   // float4 (4 elem) chunks of B

    for (int k0 = 0; k0 < K; k0 += BK) {
#pragma unroll
        for (int i = 0; i < LA; i++) {
            int idx = tid + i * 256;
            int row = idx / (BK / 4);
            int c4 = (idx % (BK / 4)) * 4;
            float4 v = make_float4(0.f, 0.f, 0.f, 0.f);
            if (bm + row < M)
                v = *reinterpret_cast<const float4*>(&A[(size_t)(bm + row) * K + k0 + c4]);
            half2 h01 = __floats2half2_rn(v.x, v.y);
            half2 h23 = __floats2half2_rn(v.z, v.w);
            *reinterpret_cast<half2*>(&As[row * LDA + c4])     = h01;
            *reinterpret_cast<half2*>(&As[row * LDA + c4 + 2]) = h23;
        }
#pragma unroll
        for (int i = 0; i < LB; i++) {
            int idx = tid + i * 256;
            int kr = idx / (BN / 4);
            int c4 = (idx % (BN / 4)) * 4;
            float4 v = *reinterpret_cast<const float4*>(&B[(size_t)(k0 + kr) * N + bn + c4]);
            half2 h01 = __floats2half2_rn(v.x, v.y);
            half2 h23 = __floats2half2_rn(v.z, v.w);
            *reinterpret_cast<half2*>(&Bs[kr * LDB + c4])     = h01;
            *reinterpret_cast<half2*>(&Bs[kr * LDB + c4 + 2]) = h23;
        }
        __syncthreads();

#pragma unroll
        for (int kk = 0; kk < BK; kk += 16) {
            wmma::fragment<wmma::matrix_a, 16, 16, 16, __half, wmma::row_major> af[FM];
            wmma::fragment<wmma::matrix_b, 16, 16, 16, __half, wmma::row_major> bf[FN];
#pragma unroll
            for (int fm = 0; fm < FM; fm++)
                wmma::load_matrix_sync(af[fm], &As[(wm * WTM + fm * 16) * LDA + kk], LDA);
#pragma unroll
            for (int fn = 0; fn < FN; fn++)
                wmma::load_matrix_sync(bf[fn], &Bs[kk * LDB + wn * WTN + fn * 16], LDB);
#pragma unroll
            for (int fm = 0; fm < FM; fm++)
#pragma unroll
                for (int fn = 0; fn < FN; fn++)
                    wmma::mma_sync(acc[fm][fn], af[fm], bf[fn], acc[fm][fn]);
        }
        __syncthreads();
    }

#pragma unroll
    for (int fm = 0; fm < FM; fm++)
#pragma unroll
        for (int fn = 0; fn < FN; fn++)
            wmma::store_matrix_sync(
                &C[(size_t)(bm + wm * WTM + fm * 16) * N + bn + wn * WTN + fn * 16],
                acc[fm][fn], N, wmma::mem_row_major);
}

// ---------------- layer-1 aggregate (CSR gather) + self + bias + relu -------
__global__ __launch_bounds__(256)
void k_agg1(const int* __restrict__ rowptr, const int* __restrict__ csrc,
            const float* __restrict__ dinv, const float* __restrict__ h1,
            const float* __restrict__ b1, float* __restrict__ y) {
    int node = (blockIdx.x * blockDim.x + threadIdx.x) >> 5;
    if (node >= N_NODES) return;
    int lane = threadIdx.x & 31;
    int beg = __ldg(&rowptr[node]);
    int end = __ldg(&rowptr[node + 1]);
    float dd = __ldg(&dinv[node]);

    float4 a0 = {0, 0, 0, 0}, a1 = {0, 0, 0, 0}, a2 = {0, 0, 0, 0}, a3 = {0, 0, 0, 0};
    const float4* H = reinterpret_cast<const float4*>(h1);
    for (int j = beg; j < end; j++) {
        int s = __ldg(&csrc[j]);
        float nrm = dd * __ldg(&dinv[s]);
        const float4* hp = H + (size_t)s * 128;
        float4 v0 = __ldg(hp + lane);
        float4 v1 = __ldg(hp + lane + 32);
        float4 v2 = __ldg(hp + lane + 64);
        float4 v3 = __ldg(hp + lane + 96);
        a0.x += v0.x * nrm; a0.y += v0.y * nrm; a0.z += v0.z * nrm; a0.w += v0.w * nrm;
        a1.x += v1.x * nrm; a1.y += v1.y * nrm; a1.z += v1.z * nrm; a1.w += v1.w * nrm;
        a2.x += v2.x * nrm; a2.y += v2.y * nrm; a2.z += v2.z * nrm; a2.w += v2.w * nrm;
        a3.x += v3.x * nrm; a3.y += v3.y * nrm; a3.z += v3.z * nrm; a3.w += v3.w * nrm;
    }
    float w = dd * dd;
    const float4* hs = H + (size_t)node * 128;
    const float4* B4 = reinterpret_cast<const float4*>(b1);
    float4* Y = reinterpret_cast<float4*>(y) + (size_t)node * 128;
    float4 accs[4] = {a0, a1, a2, a3};
#pragma unroll
    for (int kchunk = 0; kchunk < 4; kchunk++) {
        int off = lane + kchunk * 32;
        float4 h = __ldg(hs + off);
        float4 b = __ldg(B4 + off);
        float4 r;
        r.x = fmaxf(accs[kchunk].x + h.x * w + b.x, 0.f);
        r.y = fmaxf(accs[kchunk].y + h.y * w + b.y, 0.f);
        r.z = fmaxf(accs[kchunk].z + h.z * w + b.z, 0.f);
        r.w = fmaxf(accs[kchunk].w + h.w * w + b.w, 0.f);
        Y[off] = r;
    }
}

// ---------------- layer-2 aggregate + self + bias + log_softmax -> out ------
__global__ __launch_bounds__(256)
void k_agg2(const int* __restrict__ rowptr, const int* __restrict__ csrc,
            const float* __restrict__ dinv, const float* __restrict__ h2,
            const float* __restrict__ b2, float* __restrict__ out) {
    int node = (blockIdx.x * blockDim.x + threadIdx.x) >> 5;
    if (node >= N_NODES) return;
    int lane = threadIdx.x & 31;
    int beg = __ldg(&rowptr[node]);
    int end = __ldg(&rowptr[node + 1]);
    float dd = __ldg(&dinv[node]);

    float2 acc = {0, 0};
    const float2* H2 = reinterpret_cast<const float2*>(h2);
    for (int j = beg; j < end; j++) {
        int s = __ldg(&csrc[j]);
        float nrm = dd * __ldg(&dinv[s]);
        float2 v = __ldg(H2 + (size_t)s * 32 + lane);
        acc.x += v.x * nrm;
        acc.y += v.y * nrm;
    }
    float w = dd * dd;
    float2 hv = __ldg(H2 + (size_t)node * 32 + lane);
    float2 bv = reinterpret_cast<const float2*>(b2)[lane];
    float v0 = acc.x + hv.x * w + bv.x;
    float v1 = acc.y + hv.y * w + bv.y;

    size_t base = (size_t)node * OUT_SIZE;
    out[base + 2 * lane] = v0;
    out[base + 2 * lane + 1] = v1;

    float m = fmaxf(v0, v1);
#pragma unroll
    for (int o = 16; o > 0; o >>= 1) m = fmaxf(m, __shfl_xor_sync(0xffffffffu, m, o));
    float s = expf(v0 - m) + expf(v1 - m);
#pragma unroll
    for (int o = 16; o > 0; o >>= 1) s += __shfl_xor_sync(0xffffffffu, s, o);
    float lse = m + logf(s);
    const size_t half = (size_t)N_NODES * OUT_SIZE;
    out[half + base + 2 * lane] = v0 - lse;
    out[half + base + 2 * lane + 1] = v1 - lse;
}

// ---------------- launch ----------------------------------------------------
extern "C" void kernel_launch(void* const* d_in, const int* in_sizes, int n_in,
                              void* d_out, int out_size) {
    const float* x  = (const float*)d_in[0];
    const int*   ei = (const int*)d_in[1];   // [2, E]: src row then dst row
    const float* W1 = (const float*)d_in[2];
    const float* b1 = (const float*)d_in[3];
    const float* W2 = (const float*)d_in[4];
    const float* b2 = (const float*)d_in[5];
    float* out = (float*)d_out;

    const int* src = ei;
    const int* dst = ei + N_EDGES;

    float *dinv, *h1, *y, *h2;
    int *cnt, *rowptr, *cursor, *csrc;
    cudaGetSymbolAddress((void**)&dinv,   g_dinv);
    cudaGetSymbolAddress((void**)&cnt,    g_cnt);
    cudaGetSymbolAddress((void**)&rowptr, g_rowptr);
    cudaGetSymbolAddress((void**)&cursor, g_cursor);
    cudaGetSymbolAddress((void**)&csrc,   g_csrc);
    cudaGetSymbolAddress((void**)&h1,     g_h1);
    cudaGetSymbolAddress((void**)&y,      g_y);
    cudaGetSymbolAddress((void**)&h2,     g_h2);

    // Side stream + fork/join events (created per call, never destroyed:
    // destroying a capture-participating stream would invalidate the capture;
    // ~3 calls total -> negligible host-handle leak, zero device memory).
    cudaStream_t s2;
    cudaStreamCreateWithFlags(&s2, cudaStreamNonBlocking);
    cudaEvent_t evFork, evJoin;
    cudaEventCreateWithFlags(&evFork, cudaEventDisableTiming);
    cudaEventCreateWithFlags(&evJoin, cudaEventDisableTiming);

    // fork: CSR chain on s2, concurrent with GEMM1 on the main stream
    cudaEventRecord(evFork, 0);
    cudaStreamWaitEvent(s2, evFork, 0);

    k_hist<<<(N_EDGES + 255) / 256, 256, 0, s2>>>(dst, cnt);
    k_scan<<<1, SCAN_T, 0, s2>>>(cnt, rowptr, cursor, dinv);
    k_fill<<<(N_EDGES + 255) / 256, 256, 0, s2>>>(src, dst, cursor, csrc);
    cudaEventRecord(evJoin, s2);

    // GEMM1 on main stream: h1 = x @ W1   [10000,512]x[512,512]  (fp16 MMA)
    {
        dim3 grid((N_NODES + 127) / 128, H_SIZE / 64);
        k_hgemm<128, 64, 32, 4, 2><<<grid, 256>>>(x, W1, h1, N_NODES, H_SIZE, IN_SIZE);
    }

    // join: aggregation needs both GEMM1 (main) and CSR (s2)
    cudaStreamWaitEvent(0, evJoin, 0);

    // layer-1 aggregation + relu
    k_agg1<<<(N_NODES * 32 + 255) / 256, 256>>>(rowptr, csrc, dinv, h1, b1, y);

    // GEMM2: h2 = y @ W2   [10000,512]x[512,64]  (fp16 MMA)
    {
        dim3 grid((N_NODES + 63) / 64, OUT_SIZE / 64);
        k_hgemm<64, 64, 32, 2, 4><<<grid, 256>>>(y, W2, h2, N_NODES, OUT_SIZE, H_SIZE);
    }

    // layer-2 aggregation + bias + log_softmax -> out
    k_agg2<<<(N_NODES * 32 + 255) / 256, 256>>>(rowptr, csrc, dinv, h2, b2, out);
}

// round 15
// speedup vs baseline: 1.9591x; 1.1446x over previous
#include <cuda_runtime.h>
#include <cuda_fp16.h>
#include <mma.h>
#include <cstdint>

using namespace nvcuda;

#define N_NODES 10000
#define N_EDGES 163840
#define IN_SIZE 512
#define H_SIZE 512
#define OUT_SIZE 64
#define M_PAD 10112   // padded row count (>= ceil(10000/128)*128)

// ---------------- scratch (device globals; no allocation allowed) ----------
// g_cnt starts zero (static zero-init); k_scan re-zeros it after consuming,
// so it is zero before k_hist on every graph replay.
__device__ float  g_dinv[N_NODES];
__device__ int    g_cnt[N_NODES];
__device__ int    g_rowptr[N_NODES + 1];
__device__ int    g_cursor[N_NODES];
__device__ int    g_csrc[N_EDGES];
__device__ __half g_h1[(size_t)M_PAD * H_SIZE];   // x@W1, fp16
__device__ __half g_y[(size_t)M_PAD * H_SIZE];    // relu(Â h1 + b1), fp16
__device__ __half g_h2[(size_t)M_PAD * OUT_SIZE]; // y@W2, fp16

// ---------------- CSR build -------------------------------------------------
__global__ void k_hist(const int* __restrict__ dst, int* cnt) {
    int e = blockIdx.x * blockDim.x + threadIdx.x;
    if (e < N_EDGES) atomicAdd(&cnt[dst[e]], 1);
}

// single-block scan (warp-shuffle, 2 barriers) over 10000 counts.
#define SCAN_T 1024
#define SCAN_E 10
__global__ __launch_bounds__(SCAN_T)
void k_scan(int* cnt, int* rowptr, int* cursor, float* dinv) {
    __shared__ int wsum[32];
    const int t = threadIdx.x;
    const int lane = t & 31;
    const int wid = t >> 5;
    const int base = t * SCAN_E;

    int c[SCAN_E];
    int s = 0;
#pragma unroll
    for (int i = 0; i < SCAN_E; i++) {
        int idx = base + i;
        c[i] = (idx < N_NODES) ? cnt[idx] : 0;
        s += c[i];
    }
    int ws = s;
#pragma unroll
    for (int o = 1; o < 32; o <<= 1) {
        int v = __shfl_up_sync(0xffffffffu, ws, o);
        if (lane >= o) ws += v;
    }
    if (lane == 31) wsum[wid] = ws;
    __syncthreads();
    if (wid == 0) {
        int v = wsum[lane];
#pragma unroll
        for (int o = 1; o < 32; o <<= 1) {
            int u = __shfl_up_sync(0xffffffffu, v, o);
            if (lane >= o) v += u;
        }
        wsum[lane] = v;
    }
    __syncthreads();

    int warp_excl = (wid == 0) ? 0 : wsum[wid - 1];
    int run = warp_excl + ws - s;
#pragma unroll
    for (int i = 0; i < SCAN_E; i++) {
        int idx = base + i;
        if (idx < N_NODES) {
            rowptr[idx] = run;
            cursor[idx] = run;
            dinv[idx] = rsqrtf((float)(c[i] + 1));  // +1 self loop
            cnt[idx] = 0;                            // re-zero for next replay
            run += c[i];
        }
    }
    if (t == SCAN_T - 1) rowptr[N_NODES] = wsum[31];
}

__global__ void k_fill(const int* __restrict__ src, const int* __restrict__ dst,
                       int* cursor, int* csrc) {
    int e = blockIdx.x * blockDim.x + threadIdx.x;
    if (e >= N_EDGES) return;
    int d = dst[e];
    int pos = atomicAdd(&cursor[d], 1);
    csrc[pos] = src[e];
}

// ---------------- FP16 WMMA GEMM (sync loads, single buffer) ----------------
// AHALF=false: A is fp32, converted (RN) to fp16 in the smem fill.
// AHALF=true : A is already fp16, fill is a pure uint4 copy.
// B is fp32, converted in fill. Accumulate fp32; store C as fp16 (RN) via
// elementwise accumulator-fragment conversion (same thread-element mapping
// for float/half m16n16k16 accumulators).
// C rows are padded (stores unguarded); A rows >= M read as zero.
template <int BM, int BN, int BK, int WM, int WN, bool AHALF>
__global__ __launch_bounds__(256)
void k_hgemm(const void* __restrict__ Av, const float* __restrict__ B,
             __half* __restrict__ C, int M, int N, int K) {
    constexpr int LDA = BK + 8;   // halves; multiple of 8
    constexpr int LDB = BN + 8;
    constexpr int WTM = BM / WM;
    constexpr int WTN = BN / WN;
    constexpr int FM = WTM / 16;
    constexpr int FN = WTN / 16;
    __shared__ __half As[BM * LDA];
    __shared__ __half Bs[BK * LDB];

    const int tid = threadIdx.x;
    const int wid = tid >> 5;
    const int wm = wid % WM;
    const int wn = wid / WM;
    const int bm = blockIdx.x * BM;
    const int bn = blockIdx.y * BN;

    wmma::fragment<wmma::accumulator, 16, 16, 16, float> acc[FM][FN];
#pragma unroll
    for (int fm = 0; fm < FM; fm++)
#pragma unroll
        for (int fn = 0; fn < FN; fn++) wmma::fill_fragment(acc[fm][fn], 0.0f);

    for (int k0 = 0; k0 < K; k0 += BK) {
        if (AHALF) {
            const __half* A = (const __half*)Av;
            constexpr int LAH = (BM * BK) / (8 * 256);  // uint4 (8 half) chunks
#pragma unroll
            for (int i = 0; i < LAH; i++) {
                int idx = tid + i * 256;
                int row = idx / (BK / 8);
                int c8 = (idx % (BK / 8)) * 8;
                uint4 v = make_uint4(0u, 0u, 0u, 0u);
                if (bm + row < M)
                    v = *reinterpret_cast<const uint4*>(&A[(size_t)(bm + row) * K + k0 + c8]);
                *reinterpret_cast<uint4*>(&As[row * LDA + c8]) = v;
            }
        } else {
            const float* A = (const float*)Av;
            constexpr int LA = (BM * BK) / (4 * 256);   // float4 (4 elem) chunks
#pragma unroll
            for (int i = 0; i < LA; i++) {
                int idx = tid + i * 256;
                int row = idx / (BK / 4);
                int c4 = (idx % (BK / 4)) * 4;
                float4 v = make_float4(0.f, 0.f, 0.f, 0.f);
                if (bm + row < M)
                    v = *reinterpret_cast<const float4*>(&A[(size_t)(bm + row) * K + k0 + c4]);
                *reinterpret_cast<half2*>(&As[row * LDA + c4])     = __floats2half2_rn(v.x, v.y);
                *reinterpret_cast<half2*>(&As[row * LDA + c4 + 2]) = __floats2half2_rn(v.z, v.w);
            }
        }
        {
            constexpr int LB = (BK * BN) / (4 * 256);
#pragma unroll
            for (int i = 0; i < LB; i++) {
                int idx = tid + i * 256;
                int kr = idx / (BN / 4);
                int c4 = (idx % (BN / 4)) * 4;
                float4 v = *reinterpret_cast<const float4*>(&B[(size_t)(k0 + kr) * N + bn + c4]);
                *reinterpret_cast<half2*>(&Bs[kr * LDB + c4])     = __floats2half2_rn(v.x, v.y);
                *reinterpret_cast<half2*>(&Bs[kr * LDB + c4 + 2]) = __floats2half2_rn(v.z, v.w);
            }
        }
        __syncthreads();

#pragma unroll
        for (int kk = 0; kk < BK; kk += 16) {
            wmma::fragment<wmma::matrix_a, 16, 16, 16, __half, wmma::row_major> af[FM];
            wmma::fragment<wmma::matrix_b, 16, 16, 16, __half, wmma::row_major> bf[FN];
#pragma unroll
            for (int fm = 0; fm < FM; fm++)
                wmma::load_matrix_sync(af[fm], &As[(wm * WTM + fm * 16) * LDA + kk], LDA);
#pragma unroll
            for (int fn = 0; fn < FN; fn++)
                wmma::load_matrix_sync(bf[fn], &Bs[kk * LDB + wn * WTN + fn * 16], LDB);
#pragma unroll
            for (int fm = 0; fm < FM; fm++)
#pragma unroll
                for (int fn = 0; fn < FN; fn++)
                    wmma::mma_sync(acc[fm][fn], af[fm], bf[fn], acc[fm][fn]);
        }
        __syncthreads();
    }

#pragma unroll
    for (int fm = 0; fm < FM; fm++)
#pragma unroll
        for (int fn = 0; fn < FN; fn++) {
            wmma::fragment<wmma::accumulator, 16, 16, 16, __half> hacc;
#pragma unroll
            for (int e = 0; e < hacc.num_elements; e++)
                hacc.x[e] = __float2half_rn(acc[fm][fn].x[e]);
            wmma::store_matrix_sync(
                &C[(size_t)(bm + wm * WTM + fm * 16) * N + bn + wn * WTN + fn * 16],
                hacc, N, wmma::mem_row_major);
        }
}

// ---------------- layer-1 aggregate (CSR gather, fp16 in/out) ---------------
// h1 is fp16 (row = 512 halves = 64 uint4). Accumulate fp32; write y fp16.
__global__ __launch_bounds__(256)
void k_agg1(const int* __restrict__ rowptr, const int* __restrict__ csrc,
            const float* __restrict__ dinv, const __half* __restrict__ h1,
            const float* __restrict__ b1, __half* __restrict__ y) {
    int node = (blockIdx.x * blockDim.x + threadIdx.x) >> 5;
    if (node >= N_NODES) return;
    int lane = threadIdx.x & 31;
    int beg = __ldg(&rowptr[node]);
    int end = __ldg(&rowptr[node + 1]);
    float dd = __ldg(&dinv[node]);

    // 16 halves per lane: 2 uint4 chunks (lane, lane+32) of the 64-uint4 row
    float2 a[8];
#pragma unroll
    for (int i = 0; i < 8; i++) a[i] = make_float2(0.f, 0.f);

    const uint4* H = reinterpret_cast<const uint4*>(h1);
    for (int j = beg; j < end; j++) {
        int s = __ldg(&csrc[j]);
        float nrm = dd * __ldg(&dinv[s]);
        uint4 q0 = __ldg(H + (size_t)s * 64 + lane);
        uint4 q1 = __ldg(H + (size_t)s * 64 + lane + 32);
        const half2* p0 = reinterpret_cast<const half2*>(&q0);
        const half2* p1 = reinterpret_cast<const half2*>(&q1);
#pragma unroll
        for (int i = 0; i < 4; i++) {
            float2 f0 = __half22float2(p0[i]);
            float2 f1 = __half22float2(p1[i]);
            a[i].x     += f0.x * nrm; a[i].y     += f0.y * nrm;
            a[i + 4].x += f1.x * nrm; a[i + 4].y += f1.y * nrm;
        }
    }

    float w = dd * dd;
    uint4 s0 = __ldg(H + (size_t)node * 64 + lane);
    uint4 s1 = __ldg(H + (size_t)node * 64 + lane + 32);
    const half2* q0 = reinterpret_cast<const half2*>(&s0);
    const half2* q1 = reinterpret_cast<const half2*>(&s1);
    // bias: halves [lane*8, lane*8+8) and [(lane+32)*8, ...): float4 idx lane*2(+1), (lane+32)*2(+1)
    const float4* B4 = reinterpret_cast<const float4*>(b1);
    float4 b0 = __ldg(B4 + lane * 2);
    float4 b1v = __ldg(B4 + lane * 2 + 1);
    float4 b2v = __ldg(B4 + (lane + 32) * 2);
    float4 b3 = __ldg(B4 + (lane + 32) * 2 + 1);
    float bb[16] = {b0.x, b0.y, b0.z, b0.w, b1v.x, b1v.y, b1v.z, b1v.w,
                    b2v.x, b2v.y, b2v.z, b2v.w, b3.x, b3.y, b3.z, b3.w};

    uint4 o0, o1;
    half2* r0 = reinterpret_cast<half2*>(&o0);
    half2* r1 = reinterpret_cast<half2*>(&o1);
#pragma unroll
    for (int i = 0; i < 4; i++) {
        float2 f0 = __half22float2(q0[i]);
        float2 f1 = __half22float2(q1[i]);
        float vx0 = fmaxf(a[i].x + f0.x * w + bb[i * 2 + 0], 0.f);
        float vy0 = fmaxf(a[i].y + f0.y * w + bb[i * 2 + 1], 0.f);
        float vx1 = fmaxf(a[i + 4].x + f1.x * w + bb[8 + i * 2 + 0], 0.f);
        float vy1 = fmaxf(a[i + 4].y + f1.y * w + bb[8 + i * 2 + 1], 0.f);
        r0[i] = __floats2half2_rn(vx0, vy0);
        r1[i] = __floats2half2_rn(vx1, vy1);
    }
    uint4* Y = reinterpret_cast<uint4*>(y) + (size_t)node * 64;
    Y[lane] = o0;
    Y[lane + 32] = o1;
}

// ---------------- layer-2 aggregate + bias + log_softmax -> out (fp32) ------
// h2 is fp16 (row = 64 halves = 32 half2); lane handles 2 columns.
__global__ __launch_bounds__(256)
void k_agg2(const int* __restrict__ rowptr, const int* __restrict__ csrc,
            const float* __restrict__ dinv, const __half* __restrict__ h2,
            const float* __restrict__ b2, float* __restrict__ out) {
    int node = (blockIdx.x * blockDim.x + threadIdx.x) >> 5;
    if (node >= N_NODES) return;
    int lane = threadIdx.x & 31;
    int beg = __ldg(&rowptr[node]);
    int end = __ldg(&rowptr[node + 1]);
    float dd = __ldg(&dinv[node]);

    float2 acc = {0, 0};
    const half2* H2 = reinterpret_cast<const half2*>(h2);
    for (int j = beg; j < end; j++) {
        int s = __ldg(&csrc[j]);
        float nrm = dd * __ldg(&dinv[s]);
        float2 v = __half22float2(__ldg(H2 + (size_t)s * 32 + lane));
        acc.x += v.x * nrm;
        acc.y += v.y * nrm;
    }
    float w = dd * dd;
    float2 hv = __half22float2(__ldg(H2 + (size_t)node * 32 + lane));
    float2 bv = reinterpret_cast<const float2*>(b2)[lane];
    float v0 = acc.x + hv.x * w + bv.x;
    float v1 = acc.y + hv.y * w + bv.y;

    size_t base = (size_t)node * OUT_SIZE;
    out[base + 2 * lane] = v0;
    out[base + 2 * lane + 1] = v1;

    float m = fmaxf(v0, v1);
#pragma unroll
    for (int o = 16; o > 0; o >>= 1) m = fmaxf(m, __shfl_xor_sync(0xffffffffu, m, o));
    float s = expf(v0 - m) + expf(v1 - m);
#pragma unroll
    for (int o = 16; o > 0; o >>= 1) s += __shfl_xor_sync(0xffffffffu, s, o);
    float lse = m + logf(s);
    const size_t half_off = (size_t)N_NODES * OUT_SIZE;
    out[half_off + base + 2 * lane] = v0 - lse;
    out[half_off + base + 2 * lane + 1] = v1 - lse;
}

// ---------------- launch ----------------------------------------------------
extern "C" void kernel_launch(void* const* d_in, const int* in_sizes, int n_in,
                              void* d_out, int out_size) {
    const float* x  = (const float*)d_in[0];
    const int*   ei = (const int*)d_in[1];   // [2, E]: src row then dst row
    const float* W1 = (const float*)d_in[2];
    const float* b1 = (const float*)d_in[3];
    const float* W2 = (const float*)d_in[4];
    const float* b2 = (const float*)d_in[5];
    float* out = (float*)d_out;

    const int* src = ei;
    const int* dst = ei + N_EDGES;

    float *dinv;
    __half *h1, *y, *h2;
    int *cnt, *rowptr, *cursor, *csrc;
    cudaGetSymbolAddress((void**)&dinv,   g_dinv);
    cudaGetSymbolAddress((void**)&cnt,    g_cnt);
    cudaGetSymbolAddress((void**)&rowptr, g_rowptr);
    cudaGetSymbolAddress((void**)&cursor, g_cursor);
    cudaGetSymbolAddress((void**)&csrc,   g_csrc);
    cudaGetSymbolAddress((void**)&h1,     g_h1);
    cudaGetSymbolAddress((void**)&y,      g_y);
    cudaGetSymbolAddress((void**)&h2,     g_h2);

    // Side stream + fork/join events (created per call, never destroyed:
    // destroying a capture-participating stream would invalidate the capture;
    // ~3 calls total -> negligible host-handle leak, zero device memory).
    cudaStream_t s2;
    cudaStreamCreateWithFlags(&s2, cudaStreamNonBlocking);
    cudaEvent_t evFork, evJoin;
    cudaEventCreateWithFlags(&evFork, cudaEventDisableTiming);
    cudaEventCreateWithFlags(&evJoin, cudaEventDisableTiming);

    // fork: CSR chain on s2, concurrent with GEMM1 on the main stream
    cudaEventRecord(evFork, 0);
    cudaStreamWaitEvent(s2, evFork, 0);

    k_hist<<<(N_EDGES + 255) / 256, 256, 0, s2>>>(dst, cnt);
    k_scan<<<1, SCAN_T, 0, s2>>>(cnt, rowptr, cursor, dinv);
    k_fill<<<(N_EDGES + 255) / 256, 256, 0, s2>>>(src, dst, cursor, csrc);
    cudaEventRecord(evJoin, s2);

    // GEMM1 on main stream: h1 = x @ W1 (fp32 in, fp16 out)
    {
        dim3 grid((N_NODES + 127) / 128, H_SIZE / 64);
        k_hgemm<128, 64, 32, 4, 2, false><<<grid, 256>>>(x, W1, h1, N_NODES, H_SIZE, IN_SIZE);
    }

    // join: aggregation needs both GEMM1 (main) and CSR (s2)
    cudaStreamWaitEvent(0, evJoin, 0);

    // layer-1 aggregation + relu (fp16 gather, fp32 math, fp16 out)
    k_agg1<<<(N_NODES * 32 + 255) / 256, 256>>>(rowptr, csrc, dinv, h1, b1, y);

    // GEMM2: h2 = y @ W2 (fp16 A pure copy, fp16 out)
    {
        dim3 grid((N_NODES + 63) / 64, OUT_SIZE / 64);
        k_hgemm<64, 64, 32, 2, 4, true><<<grid, 256>>>(y, W2, h2, N_NODES, OUT_SIZE, H_SIZE);
    }

    // layer-2 aggregation + bias + log_softmax -> out (fp32)
    k_agg2<<<(N_NODES * 32 + 255) / 256, 256>>>(rowptr, csrc, dinv, h2, b2, out);
}

// round 16
// speedup vs baseline: 2.5457x; 1.2994x over previous
#include <cuda_runtime.h>
#include <cuda_fp16.h>
#include <mma.h>
#include <cstdint>

using namespace nvcuda;

#define N_NODES 10000
#define N_EDGES 163840
#define IN_SIZE 512
#define H_SIZE 512
#define OUT_SIZE 64
#define M_PAD 10112   // padded row count (>= ceil(10000/128)*128)

// ---------------- scratch (device globals; no allocation allowed) ----------
// All static zero-init. g_cnt is re-zeroed by k_scan each run. Tail rows of
// g_xh / g_y (10000..10111) are never written -> stay zero -> GEMM loads are
// unguarded over M_PAD rows.
__device__ float  g_dinv[N_NODES];
__device__ int    g_cnt[N_NODES];
__device__ int    g_rowptr[N_NODES + 1];
__device__ int    g_cursor[N_NODES];
__device__ int    g_csrc[N_EDGES];
__device__ __half g_xh[(size_t)M_PAD * IN_SIZE];  // x, fp16
__device__ __half g_w1h[IN_SIZE * H_SIZE];        // W1, fp16
__device__ __half g_w2h[H_SIZE * OUT_SIZE];       // W2, fp16
__device__ __half g_h1[(size_t)M_PAD * H_SIZE];   // x@W1, fp16
__device__ __half g_y[(size_t)M_PAD * H_SIZE];    // relu(Â h1 + b1), fp16
__device__ __half g_h2[(size_t)M_PAD * OUT_SIZE]; // y@W2, fp16

// ---------------- cp.async helpers ------------------------------------------
__device__ __forceinline__ void cp_async16(void* smem, const void* gmem) {
    uint32_t s = (uint32_t)__cvta_generic_to_shared(smem);
    asm volatile("cp.async.cg.shared.global [%0], [%1], 16;" :: "r"(s), "l"(gmem));
}
__device__ __forceinline__ void cp_commit() { asm volatile("cp.async.commit_group;"); }
template <int N>
__device__ __forceinline__ void cp_wait() { asm volatile("cp.async.wait_group %0;" :: "n"(N)); }

// ---------------- fp32 -> fp16 conversions -----------------------------------
// x (N_NODES x IN_SIZE) and W1 (IN_SIZE x H_SIZE) in one launch.
__global__ void k_cvt_xw(const float* __restrict__ x, __half* __restrict__ xh,
                         const float* __restrict__ w1, __half* __restrict__ w1h) {
    const int n1 = N_NODES * IN_SIZE / 4;
    const int n2 = IN_SIZE * H_SIZE / 4;
    int i = blockIdx.x * blockDim.x + threadIdx.x;
    if (i < n1) {
        float4 v = reinterpret_cast<const float4*>(x)[i];
        half2* o = reinterpret_cast<half2*>(xh) + i * 2;
        o[0] = __floats2half2_rn(v.x, v.y);
        o[1] = __floats2half2_rn(v.z, v.w);
    } else if (i < n1 + n2) {
        int j = i - n1;
        float4 v = reinterpret_cast<const float4*>(w1)[j];
        half2* o = reinterpret_cast<half2*>(w1h) + j * 2;
        o[0] = __floats2half2_rn(v.x, v.y);
        o[1] = __floats2half2_rn(v.z, v.w);
    }
}

__global__ void k_cvt_w2(const float* __restrict__ w2, __half* __restrict__ w2h) {
    int i = blockIdx.x * blockDim.x + threadIdx.x;
    const int n = H_SIZE * OUT_SIZE / 4;
    if (i >= n) return;
    float4 v = reinterpret_cast<const float4*>(w2)[i];
    half2* o = reinterpret_cast<half2*>(w2h) + i * 2;
    o[0] = __floats2half2_rn(v.x, v.y);
    o[1] = __floats2half2_rn(v.z, v.w);
}

// ---------------- CSR build -------------------------------------------------
__global__ void k_hist(const int* __restrict__ dst, int* cnt) {
    int e = blockIdx.x * blockDim.x + threadIdx.x;
    if (e < N_EDGES) atomicAdd(&cnt[dst[e]], 1);
}

#define SCAN_T 1024
#define SCAN_E 10
__global__ __launch_bounds__(SCAN_T)
void k_scan(int* cnt, int* rowptr, int* cursor, float* dinv) {
    __shared__ int wsum[32];
    const int t = threadIdx.x;
    const int lane = t & 31;
    const int wid = t >> 5;
    const int base = t * SCAN_E;

    int c[SCAN_E];
    int s = 0;
#pragma unroll
    for (int i = 0; i < SCAN_E; i++) {
        int idx = base + i;
        c[i] = (idx < N_NODES) ? cnt[idx] : 0;
        s += c[i];
    }
    int ws = s;
#pragma unroll
    for (int o = 1; o < 32; o <<= 1) {
        int v = __shfl_up_sync(0xffffffffu, ws, o);
        if (lane >= o) ws += v;
    }
    if (lane == 31) wsum[wid] = ws;
    __syncthreads();
    if (wid == 0) {
        int v = wsum[lane];
#pragma unroll
        for (int o = 1; o < 32; o <<= 1) {
            int u = __shfl_up_sync(0xffffffffu, v, o);
            if (lane >= o) v += u;
        }
        wsum[lane] = v;
    }
    __syncthreads();

    int warp_excl = (wid == 0) ? 0 : wsum[wid - 1];
    int run = warp_excl + ws - s;
#pragma unroll
    for (int i = 0; i < SCAN_E; i++) {
        int idx = base + i;
        if (idx < N_NODES) {
            rowptr[idx] = run;
            cursor[idx] = run;
            dinv[idx] = rsqrtf((float)(c[i] + 1));  // +1 self loop
            cnt[idx] = 0;                            // re-zero for next replay
            run += c[i];
        }
    }
    if (t == SCAN_T - 1) rowptr[N_NODES] = wsum[31];
}

__global__ void k_fill(const int* __restrict__ src, const int* __restrict__ dst,
                       int* cursor, int* csrc) {
    int e = blockIdx.x * blockDim.x + threadIdx.x;
    if (e >= N_EDGES) return;
    int d = dst[e];
    int pos = atomicAdd(&cursor[d], 1);
    csrc[pos] = src[e];
}

// ---------------- FP16 GEMM (all-fp16 inputs, cp.async 2-stage pipeline) ----
// A [M_PAD, K] fp16, B [K, N] fp16, C [M_PAD, N] fp16 (fp32 accumulate).
// Loads unguarded (buffers padded to M_PAD; tails zero).
template <int BM, int BN, int BK, int WM, int WN>
__global__ __launch_bounds__(256)
void k_hgemm(const __half* __restrict__ A, const __half* __restrict__ B,
             __half* __restrict__ C, int N, int K) {
    constexpr int LDA = BK + 8;   // halves; 80B rows (conflict-free LDSM)
    constexpr int LDB = BN + 8;   // halves; 16B-aligned pitch
    constexpr int WTM = BM / WM;
    constexpr int WTN = BN / WN;
    constexpr int FM = WTM / 16;
    constexpr int FN = WTN / 16;
    __shared__ __half As[2][BM * LDA];
    __shared__ __half Bs[2][BK * LDB];

    const int tid = threadIdx.x;
    const int wid = tid >> 5;
    const int wm = wid % WM;
    const int wn = wid / WM;
    const int bm = blockIdx.x * BM;
    const int bn = blockIdx.y * BN;

    wmma::fragment<wmma::accumulator, 16, 16, 16, float> acc[FM][FN];
#pragma unroll
    for (int fm = 0; fm < FM; fm++)
#pragma unroll
        for (int fn = 0; fn < FN; fn++) wmma::fill_fragment(acc[fm][fn], 0.0f);

    constexpr int CA = (BM * BK) / (8 * 256);   // 16B chunks of A per thread
    constexpr int CB = (BK * BN) / (8 * 256);   // 16B chunks of B per thread

    auto load_stage = [&](int stg, int k0) {
#pragma unroll
        for (int i = 0; i < CA; i++) {
            int idx = tid + i * 256;
            int row = idx / (BK / 8);
            int c8 = (idx % (BK / 8)) * 8;
            cp_async16(&As[stg][row * LDA + c8],
                       &A[(size_t)(bm + row) * K + k0 + c8]);
        }
#pragma unroll
        for (int i = 0; i < CB; i++) {
            int idx = tid + i * 256;
            int kr = idx / (BN / 8);
            int c8 = (idx % (BN / 8)) * 8;
            cp_async16(&Bs[stg][kr * LDB + c8],
                       &B[(size_t)(k0 + kr) * N + bn + c8]);
        }
        cp_commit();
    };

    const int S = K / BK;
    load_stage(0, 0);

    for (int s = 0; s < S; s++) {
        int buf = s & 1;
        if (s + 1 < S) {
            load_stage(buf ^ 1, (s + 1) * BK);
            cp_wait<1>();
        } else {
            cp_wait<0>();
        }
        __syncthreads();

#pragma unroll
        for (int kk = 0; kk < BK; kk += 16) {
            wmma::fragment<wmma::matrix_a, 16, 16, 16, __half, wmma::row_major> af[FM];
            wmma::fragment<wmma::matrix_b, 16, 16, 16, __half, wmma::row_major> bf[FN];
#pragma unroll
            for (int fm = 0; fm < FM; fm++)
                wmma::load_matrix_sync(af[fm], &As[buf][(wm * WTM + fm * 16) * LDA + kk], LDA);
#pragma unroll
            for (int fn = 0; fn < FN; fn++)
                wmma::load_matrix_sync(bf[fn], &Bs[buf][kk * LDB + wn * WTN + fn * 16], LDB);
#pragma unroll
            for (int fm = 0; fm < FM; fm++)
#pragma unroll
                for (int fn = 0; fn < FN; fn++)
                    wmma::mma_sync(acc[fm][fn], af[fm], bf[fn], acc[fm][fn]);
        }
        __syncthreads();
    }

#pragma unroll
    for (int fm = 0; fm < FM; fm++)
#pragma unroll
        for (int fn = 0; fn < FN; fn++) {
            wmma::fragment<wmma::accumulator, 16, 16, 16, __half> hacc;
#pragma unroll
            for (int e = 0; e < hacc.num_elements; e++)
                hacc.x[e] = __float2half_rn(acc[fm][fn].x[e]);
            wmma::store_matrix_sync(
                &C[(size_t)(bm + wm * WTM + fm * 16) * N + bn + wn * WTN + fn * 16],
                hacc, N, wmma::mem_row_major);
        }
}

// ---------------- layer-1 aggregate (CSR gather, fp16 in/out) ---------------
__global__ __launch_bounds__(256)
void k_agg1(const int* __restrict__ rowptr, const int* __restrict__ csrc,
            const float* __restrict__ dinv, const __half* __restrict__ h1,
            const float* __restrict__ b1, __half* __restrict__ y) {
    int node = (blockIdx.x * blockDim.x + threadIdx.x) >> 5;
    if (node >= N_NODES) return;
    int lane = threadIdx.x & 31;
    int beg = __ldg(&rowptr[node]);
    int end = __ldg(&rowptr[node + 1]);
    float dd = __ldg(&dinv[node]);

    float2 a[8];
#pragma unroll
    for (int i = 0; i < 8; i++) a[i] = make_float2(0.f, 0.f);

    const uint4* H = reinterpret_cast<const uint4*>(h1);
    for (int j = beg; j < end; j++) {
        int s = __ldg(&csrc[j]);
        float nrm = dd * __ldg(&dinv[s]);
        uint4 q0 = __ldg(H + (size_t)s * 64 + lane);
        uint4 q1 = __ldg(H + (size_t)s * 64 + lane + 32);
        const half2* p0 = reinterpret_cast<const half2*>(&q0);
        const half2* p1 = reinterpret_cast<const half2*>(&q1);
#pragma unroll
        for (int i = 0; i < 4; i++) {
            float2 f0 = __half22float2(p0[i]);
            float2 f1 = __half22float2(p1[i]);
            a[i].x     += f0.x * nrm; a[i].y     += f0.y * nrm;
            a[i + 4].x += f1.x * nrm; a[i + 4].y += f1.y * nrm;
        }
    }

    float w = dd * dd;
    uint4 s0 = __ldg(H + (size_t)node * 64 + lane);
    uint4 s1 = __ldg(H + (size_t)node * 64 + lane + 32);
    const half2* q0 = reinterpret_cast<const half2*>(&s0);
    const half2* q1 = reinterpret_cast<const half2*>(&s1);
    const float4* B4 = reinterpret_cast<const float4*>(b1);
    float4 b0 = __ldg(B4 + lane * 2);
    float4 b1v = __ldg(B4 + lane * 2 + 1);
    float4 b2v = __ldg(B4 + (lane + 32) * 2);
    float4 b3 = __ldg(B4 + (lane + 32) * 2 + 1);
    float bb[16] = {b0.x, b0.y, b0.z, b0.w, b1v.x, b1v.y, b1v.z, b1v.w,
                    b2v.x, b2v.y, b2v.z, b2v.w, b3.x, b3.y, b3.z, b3.w};

    uint4 o0, o1;
    half2* r0 = reinterpret_cast<half2*>(&o0);
    half2* r1 = reinterpret_cast<half2*>(&o1);
#pragma unroll
    for (int i = 0; i < 4; i++) {
        float2 f0 = __half22float2(q0[i]);
        float2 f1 = __half22float2(q1[i]);
        float vx0 = fmaxf(a[i].x + f0.x * w + bb[i * 2 + 0], 0.f);
        float vy0 = fmaxf(a[i].y + f0.y * w + bb[i * 2 + 1], 0.f);
        float vx1 = fmaxf(a[i + 4].x + f1.x * w + bb[8 + i * 2 + 0], 0.f);
        float vy1 = fmaxf(a[i + 4].y + f1.y * w + bb[8 + i * 2 + 1], 0.f);
        r0[i] = __floats2half2_rn(vx0, vy0);
        r1[i] = __floats2half2_rn(vx1, vy1);
    }
    uint4* Y = reinterpret_cast<uint4*>(y) + (size_t)node * 64;
    Y[lane] = o0;
    Y[lane + 32] = o1;
}

// ---------------- layer-2 aggregate + bias + log_softmax -> out (fp32) ------
__global__ __launch_bounds__(256)
void k_agg2(const int* __restrict__ rowptr, const int* __restrict__ csrc,
            const float* __restrict__ dinv, const __half* __restrict__ h2,
            const float* __restrict__ b2, float* __restrict__ out) {
    int node = (blockIdx.x * blockDim.x + threadIdx.x) >> 5;
    if (node >= N_NODES) return;
    int lane = threadIdx.x & 31;
    int beg = __ldg(&rowptr[node]);
    int end = __ldg(&rowptr[node + 1]);
    float dd = __ldg(&dinv[node]);

    float2 acc = {0, 0};
    const half2* H2 = reinterpret_cast<const half2*>(h2);
    for (int j = beg; j < end; j++) {
        int s = __ldg(&csrc[j]);
        float nrm = dd * __ldg(&dinv[s]);
        float2 v = __half22float2(__ldg(H2 + (size_t)s * 32 + lane));
        acc.x += v.x * nrm;
        acc.y += v.y * nrm;
    }
    float w = dd * dd;
    float2 hv = __half22float2(__ldg(H2 + (size_t)node * 32 + lane));
    float2 bv = reinterpret_cast<const float2*>(b2)[lane];
    float v0 = acc.x + hv.x * w + bv.x;
    float v1 = acc.y + hv.y * w + bv.y;

    size_t base = (size_t)node * OUT_SIZE;
    out[base + 2 * lane] = v0;
    out[base + 2 * lane + 1] = v1;

    float m = fmaxf(v0, v1);
#pragma unroll
    for (int o = 16; o > 0; o >>= 1) m = fmaxf(m, __shfl_xor_sync(0xffffffffu, m, o));
    float s = expf(v0 - m) + expf(v1 - m);
#pragma unroll
    for (int o = 16; o > 0; o >>= 1) s += __shfl_xor_sync(0xffffffffu, s, o);
    float lse = m + logf(s);
    const size_t half_off = (size_t)N_NODES * OUT_SIZE;
    out[half_off + base + 2 * lane] = v0 - lse;
    out[half_off + base + 2 * lane + 1] = v1 - lse;
}

// ---------------- launch ----------------------------------------------------
extern "C" void kernel_launch(void* const* d_in, const int* in_sizes, int n_in,
                              void* d_out, int out_size) {
    const float* x  = (const float*)d_in[0];
    const int*   ei = (const int*)d_in[1];   // [2, E]: src row then dst row
    const float* W1 = (const float*)d_in[2];
    const float* b1 = (const float*)d_in[3];
    const float* W2 = (const float*)d_in[4];
    const float* b2 = (const float*)d_in[5];
    float* out = (float*)d_out;

    const int* src = ei;
    const int* dst = ei + N_EDGES;

    float *dinv;
    __half *xh, *w1h, *w2h, *h1, *y, *h2;
    int *cnt, *rowptr, *cursor, *csrc;
    cudaGetSymbolAddress((void**)&dinv,   g_dinv);
    cudaGetSymbolAddress((void**)&cnt,    g_cnt);
    cudaGetSymbolAddress((void**)&rowptr, g_rowptr);
    cudaGetSymbolAddress((void**)&cursor, g_cursor);
    cudaGetSymbolAddress((void**)&csrc,   g_csrc);
    cudaGetSymbolAddress((void**)&xh,     g_xh);
    cudaGetSymbolAddress((void**)&w1h,    g_w1h);
    cudaGetSymbolAddress((void**)&w2h,    g_w2h);
    cudaGetSymbolAddress((void**)&h1,     g_h1);
    cudaGetSymbolAddress((void**)&y,      g_y);
    cudaGetSymbolAddress((void**)&h2,     g_h2);

    // Side stream + fork/join events (created per call, never destroyed:
    // ~3 calls total -> negligible host-handle leak, zero device memory).
    cudaStream_t s2;
    cudaStreamCreateWithFlags(&s2, cudaStreamNonBlocking);
    cudaEvent_t evFork, evJoin;
    cudaEventCreateWithFlags(&evFork, cudaEventDisableTiming);
    cudaEventCreateWithFlags(&evJoin, cudaEventDisableTiming);

    // fork: CSR chain + W2 conversion on s2, concurrent with cvt+GEMM1 on main
    cudaEventRecord(evFork, 0);
    cudaStreamWaitEvent(s2, evFork, 0);

    k_hist<<<(N_EDGES + 255) / 256, 256, 0, s2>>>(dst, cnt);
    k_scan<<<1, SCAN_T, 0, s2>>>(cnt, rowptr, cursor, dinv);
    k_fill<<<(N_EDGES + 255) / 256, 256, 0, s2>>>(src, dst, cursor, csrc);
    k_cvt_w2<<<(H_SIZE * OUT_SIZE / 4 + 255) / 256, 256, 0, s2>>>(W2, w2h);
    cudaEventRecord(evJoin, s2);

    // main: convert x + W1 to fp16, then GEMM1 (all-fp16, pipelined)
    {
        int total = N_NODES * IN_SIZE / 4 + IN_SIZE * H_SIZE / 4;
        k_cvt_xw<<<(total + 255) / 256, 256>>>(x, xh, W1, w1h);
    }
    {
        dim3 grid(M_PAD / 128, H_SIZE / 64);
        k_hgemm<128, 64, 32, 4, 2><<<grid, 256>>>(xh, w1h, h1, H_SIZE, IN_SIZE);
    }

    // join: aggregation needs GEMM1 (main) + CSR & W2 (s2)
    cudaStreamWaitEvent(0, evJoin, 0);

    // layer-1 aggregation + relu (fp16 gather, fp32 math, fp16 out)
    k_agg1<<<(N_NODES * 32 + 255) / 256, 256>>>(rowptr, csrc, dinv, h1, b1, y);

    // GEMM2: h2 = y @ W2 (all-fp16, pipelined)
    {
        dim3 grid((N_NODES + 63) / 64, OUT_SIZE / 64);
        k_hgemm<64, 64, 32, 2, 4><<<grid, 256>>>(y, w2h, h2, OUT_SIZE, H_SIZE);
    }

    // layer-2 aggregation + bias + log_softmax -> out (fp32)
    k_agg2<<<(N_NODES * 32 + 255) / 256, 256>>>(rowptr, csrc, dinv, h2, b2, out);
}